// round 12
// baseline (speedup 1.0000x reference)
#include <cuda_runtime.h>
#include <cuda_bf16.h>
#include <cstdint>

#define NN 4096
#define DD 512
#define F1V 64
#define HH 4
#define MAXNBR 128

__device__ __forceinline__ uint32_t smem_u32(const void* p) {
    uint32_t a;
    asm("{ .reg .u64 t; cvta.to.shared.u64 t, %1; cvt.u32.u64 %0, t; }" : "=r"(a) : "l"(p));
    return a;
}
__device__ __forceinline__ void mma_bf16(float* c, const uint32_t* a, const uint32_t* b) {
    asm volatile(
        "mma.sync.aligned.m16n8k16.row.col.f32.bf16.bf16.f32 "
        "{%0,%1,%2,%3}, {%4,%5,%6,%7}, {%8,%9}, {%0,%1,%2,%3};"
        : "+f"(c[0]), "+f"(c[1]), "+f"(c[2]), "+f"(c[3])
        : "r"(a[0]), "r"(a[1]), "r"(a[2]), "r"(a[3]), "r"(b[0]), "r"(b[1]));
}
__device__ __forceinline__ void ldsm4(uint32_t* r, uint32_t addr) {
    asm volatile("ldmatrix.sync.aligned.m8n8.x4.shared.b16 {%0,%1,%2,%3}, [%4];"
        : "=r"(r[0]), "=r"(r[1]), "=r"(r[2]), "=r"(r[3]) : "r"(addr));
}
__device__ __forceinline__ void split_bf(float f, unsigned short& hi, unsigned short& lo) {
    __nv_bfloat16 h = __float2bfloat16(f);
    float r = f - __bfloat162float(h);
    __nv_bfloat16 l = __float2bfloat16(r);
    hi = *reinterpret_cast<unsigned short*>(&h);
    lo = *reinterpret_cast<unsigned short*>(&l);
}
#define CP_ASYNC16(sa, gp) \
    asm volatile("cp.async.cg.shared.global [%0], [%1], 16;" :: "r"(sa), "l"(gp) : "memory")
#define CP_COMMIT() asm volatile("cp.async.commit_group;" ::: "memory")
#define CP_WAIT1()  asm volatile("cp.async.wait_group 1;" ::: "memory")

// ---------------- device scratch (static, no allocation) ----------------
__device__ int      g_cnt[NN];
__device__ int      g_cols[NN * MAXNBR];
__device__ uint16_t g_xhi[NN * DD];
__device__ uint16_t g_xlo[NN * DD];
__device__ uint16_t g_Wthi[HH * F1V * DD];     // [h][n][k] transposed = [256][512]
__device__ uint16_t g_Wtlo[HH * F1V * DD];
__device__ uint16_t g_Wathi[F1V * 256];        // [n][k] = [64][256]
__device__ uint16_t g_Watlo[F1V * 256];
__device__ float    g_Wh[HH * NN * F1V];       // [h][n][64]
__device__ float    g_src[HH * NN];
__device__ float    g_dst[HH * NN];
__device__ uint16_t g_cat_hi[NN * 256];        // [n][h*64+f]
__device__ uint16_t g_cat_lo[NN * 256];
__device__ float    g_Whc[NN * F1V];
__device__ float    g_srcc[NN];
__device__ float    g_dstc[NN];
__device__ float    g_t1[NN * 32];
__device__ float    g_t23[NN * 32];
__device__ float    g_z[NN * 16];

// ---------------- 1: CSR build (warp per row) ---------------------------
__global__ void k_build_csr(const float* __restrict__ adj) {
    int wid = threadIdx.x >> 5, lane = threadIdx.x & 31;
    int row = blockIdx.x * 8 + wid;
    const float4* arow = reinterpret_cast<const float4*>(adj + (size_t)row * NN);
    int cnt = 0;
    int* cols = g_cols + row * MAXNBR;
    for (int step = 0; step < 32; ++step) {
        float4 v = arow[step * 32 + lane];
        float vals[4] = {v.x, v.y, v.z, v.w};
        #pragma unroll
        for (int e = 0; e < 4; ++e) {
            bool p = vals[e] > 0.0f;
            unsigned m = __ballot_sync(0xffffffffu, p);
            if (p) {
                int pos = cnt + __popc(m & ((1u << lane) - 1u));
                if (pos < MAXNBR) cols[pos] = (step * 32 + lane) * 4 + e;
            }
            cnt += __popc(m);
        }
    }
    if (lane == 0) g_cnt[row] = cnt > MAXNBR ? MAXNBR : cnt;
}

// ---------------- 2: split x into bf16 hi/lo ----------------------------
__global__ void k_prep_x(const float* __restrict__ x) {
    int idx = blockIdx.x * 256 + threadIdx.x;
    float4 v = reinterpret_cast<const float4*>(x)[idx];
    unsigned short h0, l0, h1, l1, h2, l2, h3, l3;
    split_bf(v.x, h0, l0); split_bf(v.y, h1, l1);
    split_bf(v.z, h2, l2); split_bf(v.w, h3, l3);
    uint2 hv = make_uint2((uint32_t)h0 | ((uint32_t)h1 << 16),
                          (uint32_t)h2 | ((uint32_t)h3 << 16));
    uint2 lv = make_uint2((uint32_t)l0 | ((uint32_t)l1 << 16),
                          (uint32_t)l2 | ((uint32_t)l3 << 16));
    reinterpret_cast<uint2*>(g_xhi)[idx] = hv;
    reinterpret_cast<uint2*>(g_xlo)[idx] = lv;
}

// ---------------- 3: split+transpose weights ----------------------------
__global__ void k_prep_w(const float* __restrict__ W_heads, const float* __restrict__ W_att) {
    int idx = blockIdx.x * 256 + threadIdx.x;
    if (idx < HH * DD * F1V) {
        int n = idx & 63, k = (idx >> 6) & 511, h = idx >> 15;
        unsigned short hi, lo;
        split_bf(W_heads[idx], hi, lo);
        int o = (h * F1V + n) * DD + k;
        g_Wthi[o] = hi; g_Wtlo[o] = lo;
    } else {
        int i2 = idx - HH * DD * F1V;   // [256][64]
        int n = i2 & 63, k = i2 >> 6;
        unsigned short hi, lo;
        split_bf(W_att[i2], hi, lo);
        int o = n * 256 + k;
        g_Wathi[o] = hi; g_Watlo[o] = lo;
    }
}

// ---------------- 4: cp.async 3-stage mma GEMM, fused src/dst -----------
// M tile 64, N tile = NB4*4 cols (sel0: 128 = 2 heads; sel1: 64).
// k-chunk 16; XOR-swizzled smem rows of 32B: unit addr = r*32 + ((u^((r>>2)&1))<<4).
// stage (12288B): Ahi@0 (64 rows), Alo@2048, Bhi@4096 (up to 128 rows), Blo@8192.
template<int NB4>
__global__ void __launch_bounds__(256)
k_gemm_tc(const float* __restrict__ avec, int K, int sel) {
    constexpr int NB = NB4 * 4;
    __shared__ __align__(16) unsigned char sm[3 * 12288];
    __shared__ float s_av[256];
    __shared__ float s_sp[4][64];
    __shared__ float s_dp[4][64];

    int tid = threadIdx.x;
    int w = tid >> 5, lane = tid & 31;
    int MW = (w & 1) * 32;
    int nw = w >> 1;                 // N-block index 0..3
    int CW = nw * NB4;
    int g = lane >> 2, t = lane & 3;
    int m0 = blockIdx.x * 64;
    int nb0 = blockIdx.y * NB;       // base B-row (global head*64+n index)

    const uint16_t *Ahi, *Alo, *Bhi, *Blo;
    float *oWh, *oSrc, *oDst;
    if (sel == 0) {
        Ahi = g_xhi; Alo = g_xlo; Bhi = g_Wthi; Blo = g_Wtlo;
        oWh = g_Wh; oSrc = g_src; oDst = g_dst;
    } else {
        Ahi = g_cat_hi; Alo = g_cat_lo; Bhi = g_Wathi; Blo = g_Watlo;
        oWh = g_Whc; oSrc = g_srcc; oDst = g_dstc;
    }
    for (int i = tid; i < NB * 2; i += 256) s_av[i] = avec[nb0 * 2 + i];

    uint32_t smb = smem_u32(sm);
    int nch = K >> 4;

    // LDSM offsets (stage-relative). +16 rows => +512 bytes (swizzle bit preserved).
    int rA = MW + (lane & 15), uA = lane >> 4;
    int offA = rA * 32 + (((uA ^ ((rA >> 2) & 1))) << 4);
    int rB = CW + ((lane >> 4) << 3) + (lane & 7), uB = (lane >> 3) & 1;
    int offB = 4096 + rB * 32 + (((uB ^ ((rB >> 2) & 1))) << 4);

    // cp.async issue for chunk c into stage byte-offset stg
    auto issue = [&](int c, int stg) {
        const int nU = 256 + NB * 4;
        for (int i = tid; i < nU; i += 256) {
            uint32_t sa; const uint16_t* gp;
            if (i < 256) {
                int side = i >> 7, rw = i & 127, r = rw >> 1, u = rw & 1;
                gp = (side ? Alo : Ahi) + (size_t)(m0 + r) * K + c * 16 + u * 8;
                sa = smb + stg + side * 2048 + r * 32 + (((u ^ ((r >> 2) & 1))) << 4);
            } else {
                int j = i - 256, side = j / (NB * 2), rw = j % (NB * 2), r = rw >> 1, u = rw & 1;
                gp = (side ? Blo : Bhi) + (size_t)(nb0 + r) * K + c * 16 + u * 8;
                sa = smb + stg + 4096 + side * 4096 + r * 32 + (((u ^ ((r >> 2) & 1))) << 4);
            }
            CP_ASYNC16(sa, gp);
        }
    };

    float acc[2][NB4 / 8][4] = {};

    issue(0, 0);      CP_COMMIT();
    issue(1, 12288);  CP_COMMIT();

    for (int c = 0; c < nch; ++c) {
        CP_WAIT1();
        __syncthreads();
        if (c + 2 < nch) issue(c + 2, ((c + 2) % 3) * 12288);
        CP_COMMIT();

        uint32_t st = smb + (c % 3) * 12288;
        uint32_t ah[2][4], al[2][4], bh[NB4 / 16][4], bl[NB4 / 16][4];
        ldsm4(ah[0], st + offA);
        ldsm4(ah[1], st + offA + 512);
        ldsm4(al[0], st + 2048 + offA);
        ldsm4(al[1], st + 2048 + offA + 512);
        #pragma unroll
        for (int q2 = 0; q2 < NB4 / 16; ++q2) {
            ldsm4(bh[q2], st + offB + q2 * 512);
            ldsm4(bl[q2], st + 4096 + offB + q2 * 512);
        }
        #pragma unroll
        for (int i = 0; i < 2; ++i)
            #pragma unroll
            for (int q = 0; q < NB4 / 8; ++q) {
                float* cc = acc[i][q];
                const uint32_t* bph = &bh[q >> 1][(q & 1) * 2];
                const uint32_t* bpl = &bl[q >> 1][(q & 1) * 2];
                mma_bf16(cc, ah[i], bph);
                mma_bf16(cc, al[i], bph);
                mma_bf16(cc, ah[i], bpl);
            }
    }

    // epilogue: write Wh + fused src/dst partials
    int hb = nb0 >> 6;
    #pragma unroll
    for (int i = 0; i < 2; ++i) {
        int r0 = MW + i * 16 + g;
        float sp0 = 0, sp1 = 0, dp0 = 0, dp1 = 0;
        #pragma unroll
        for (int q = 0; q < NB4 / 8; ++q) {
            int gn = nb0 + CW + q * 8 + 2 * t;      // global N index (head*64 + col)
            int head = gn >> 6, col = gn & 63;
            float* whr = oWh + ((size_t)head * NN + m0 + r0) * 64 + col;
            *reinterpret_cast<float2*>(whr) = make_float2(acc[i][q][0], acc[i][q][1]);
            *reinterpret_cast<float2*>(whr + 8 * 64) = make_float2(acc[i][q][2], acc[i][q][3]);
            int ai = (head - hb) * 128 + col;
            float a0s = s_av[ai], a1s = s_av[ai + 1];
            float a0d = s_av[ai + 64], a1d = s_av[ai + 65];
            sp0 += acc[i][q][0] * a0s + acc[i][q][1] * a1s;
            sp1 += acc[i][q][2] * a0s + acc[i][q][3] * a1s;
            dp0 += acc[i][q][0] * a0d + acc[i][q][1] * a1d;
            dp1 += acc[i][q][2] * a0d + acc[i][q][3] * a1d;
        }
        #pragma unroll
        for (int off = 1; off < 4; off <<= 1) {
            sp0 += __shfl_xor_sync(0xffffffffu, sp0, off);
            sp1 += __shfl_xor_sync(0xffffffffu, sp1, off);
            dp0 += __shfl_xor_sync(0xffffffffu, dp0, off);
            dp1 += __shfl_xor_sync(0xffffffffu, dp1, off);
        }
        if (t == 0) {
            s_sp[nw][r0] = sp0; s_sp[nw][r0 + 8] = sp1;
            s_dp[nw][r0] = dp0; s_dp[nw][r0 + 8] = dp1;
        }
    }
    __syncthreads();
    constexpr int NH = NB / 64;          // heads per CTA (2 or 1)
    constexpr int NBLK = 64 / NB4;       // N-blocks per head (2 or 4)
    if (tid < NH * 64) {
        int h2 = tid >> 6, r = tid & 63;
        float vs = 0, vd = 0;
        #pragma unroll
        for (int b = 0; b < NBLK; ++b) {
            vs += s_sp[h2 * NBLK + b][r];
            vd += s_dp[h2 * NBLK + b][r];
        }
        int head = hb + h2;
        oSrc[head * NN + m0 + r] = vs;
        oDst[head * NN + m0 + r] = vd;
    }
}

// ---------------- 5: sparse GAT softmax + aggregate + ELU ---------------
__global__ void k_gat_aggr(const float* __restrict__ W1, int sel) {
    __shared__ float s_w[8][MAXNBR];
    __shared__ int   s_c[8][MAXNBR];
    int wid = threadIdx.x >> 5, lane = threadIdx.x & 31;
    int wg = blockIdx.x * 8 + wid;
    int h, row;
    if (sel) { h = 0; row = wg; } else { h = wg & 3; row = wg >> 2; }
    const float* Wh  = sel ? g_Whc  : g_Wh;
    const float* src = sel ? g_srcc : g_src;
    const float* dst = sel ? g_dstc : g_dst;

    int cnt = g_cnt[row];
    const int* cols = g_cols + row * MAXNBR;
    float si = src[h * NN + row];
    const float* dsth = dst + (size_t)h * NN;

    float sum = 0.0f;
    #pragma unroll
    for (int tt = 0; tt < 4; ++tt) {
        int idx = tt * 32 + lane;
        float e = 0.0f; int c = 0;
        if (idx < cnt) {
            c = cols[idx];
            float v = si + __ldg(dsth + c);
            v = v > 0.0f ? v : 0.2f * v;           // LeakyReLU (logits bounded -> no max)
            e = __expf(v);
        }
        s_w[wid][idx] = e;
        s_c[wid][idx] = c;
        sum += e;
    }
    #pragma unroll
    for (int o = 16; o; o >>= 1) sum += __shfl_xor_sync(0xffffffffu, sum, o);
    float inv = 1.0f / sum;
    __syncwarp();

    int half = lane >> 4, li = lane & 15;
    const float* WhhB = Wh + (size_t)h * NN * 64;
    float4 A0 = {0, 0, 0, 0}, A1 = {0, 0, 0, 0};
    int cntR = (cnt + 3) & ~3;
    for (int j = 0; j < cntR; j += 4) {
        int   c0 = s_c[wid][j + half],     c1 = s_c[wid][j + 2 + half];
        float w0 = s_w[wid][j + half],     w1 = s_w[wid][j + 2 + half];
        float4 v0 = __ldg(reinterpret_cast<const float4*>(WhhB + (size_t)c0 * 64) + li);
        float4 v1 = __ldg(reinterpret_cast<const float4*>(WhhB + (size_t)c1 * 64) + li);
        A0.x += w0 * v0.x; A0.y += w0 * v0.y; A0.z += w0 * v0.z; A0.w += w0 * v0.w;
        A1.x += w1 * v1.x; A1.y += w1 * v1.y; A1.z += w1 * v1.z; A1.w += w1 * v1.w;
    }
    float4 A;
    A.x = A0.x + A1.x; A.y = A0.y + A1.y; A.z = A0.z + A1.z; A.w = A0.w + A1.w;
    A.x += __shfl_xor_sync(0xffffffffu, A.x, 16);
    A.y += __shfl_xor_sync(0xffffffffu, A.y, 16);
    A.z += __shfl_xor_sync(0xffffffffu, A.z, 16);
    A.w += __shfl_xor_sync(0xffffffffu, A.w, 16);
    A.x *= inv; A.y *= inv; A.z *= inv; A.w *= inv;
    A.x = A.x > 0.0f ? A.x : __expf(A.x) - 1.0f;   // ELU
    A.y = A.y > 0.0f ? A.y : __expf(A.y) - 1.0f;
    A.z = A.z > 0.0f ? A.z : __expf(A.z) - 1.0f;
    A.w = A.w > 0.0f ? A.w : __expf(A.w) - 1.0f;

    if (sel == 0) {
        if (half == 0) {
            unsigned short h0, l0, h1, l1, h2, l2, h3, l3;
            split_bf(A.x, h0, l0); split_bf(A.y, h1, l1);
            split_bf(A.z, h2, l2); split_bf(A.w, h3, l3);
            int o2 = row * 64 + h * 16 + li;
            reinterpret_cast<uint2*>(g_cat_hi)[o2] =
                make_uint2((uint32_t)h0 | ((uint32_t)h1 << 16),
                           (uint32_t)h2 | ((uint32_t)h3 << 16));
            reinterpret_cast<uint2*>(g_cat_lo)[o2] =
                make_uint2((uint32_t)l0 | ((uint32_t)l1 << 16),
                           (uint32_t)l2 | ((uint32_t)l3 << 16));
        }
    } else {
        float acc = 0.0f;
        #pragma unroll
        for (int li2 = 0; li2 < 16; ++li2) {
            float w0 = __shfl_sync(0xffffffffu, A.x, li2);
            float w1 = __shfl_sync(0xffffffffu, A.y, li2);
            float w2 = __shfl_sync(0xffffffffu, A.z, li2);
            float w3 = __shfl_sync(0xffffffffu, A.w, li2);
            int kb = li2 * 4;
            acc += w0 * W1[kb * 32 + lane] + w1 * W1[(kb + 1) * 32 + lane]
                 + w2 * W1[(kb + 2) * 32 + lane] + w3 * W1[(kb + 3) * 32 + lane];
        }
        g_t1[(size_t)row * 32 + lane] = acc;
    }
}

// ---------------- 6: h1 = relu(nbrsum(t1)); t23 = h1@[W2|W3] ------------
__global__ void k_nbr_t23(const float* __restrict__ W2, const float* __restrict__ W3) {
    int wid = threadIdx.x >> 5, lane = threadIdx.x & 31;
    int row = blockIdx.x * 8 + wid;
    int cnt = g_cnt[row];
    const int* cols = g_cols + row * MAXNBR;
    float acc = 0.0f;
    for (int jj = 0; jj < cnt; ++jj) {
        int c = cols[jj];
        acc += g_t1[(size_t)c * 32 + lane];
    }
    float hv = fmaxf(acc, 0.0f);
    const float* W = (lane < 16) ? W2 : W3;
    int f = lane & 15;
    float acc2 = 0.0f;
    #pragma unroll
    for (int k = 0; k < 32; ++k) {
        float h = __shfl_sync(0xffffffffu, hv, k);
        acc2 += h * W[k * 16 + f];
    }
    g_t23[(size_t)row * 32 + lane] = acc2;
}

// ---------------- 7: mu/logvar = nbrsum, z = eps*exp(lv)+mu -------------
__global__ void k_final(const float* __restrict__ eps, float* __restrict__ out) {
    int wid = threadIdx.x >> 5, lane = threadIdx.x & 31;
    int row = blockIdx.x * 8 + wid;
    int cnt = g_cnt[row];
    const int* cols = g_cols + row * MAXNBR;
    float acc = 0.0f;
    for (int j = 0; j < cnt; ++j) {
        int c = cols[j];
        acc += g_t23[(size_t)c * 32 + lane];
    }
    float other = __shfl_xor_sync(0xffffffffu, acc, 16);
    size_t NNq = (size_t)NN * NN;
    if (lane < 16) {
        out[NNq + (size_t)row * 16 + lane] = acc;                          // mu
        float zz = eps[(size_t)row * 16 + lane] * __expf(other) + acc;
        g_z[(size_t)row * 16 + lane] = zz;
    } else {
        out[NNq + (size_t)NN * 16 + (size_t)row * 16 + (lane - 16)] = acc; // logvar
    }
}

// ---------------- 8: adj_rec = z @ z^T (packed f32x2 FMA) ---------------
__global__ void k_adjrec(float* __restrict__ out) {
    __shared__ float zi[64 * 17];
    __shared__ float zjT[16][64];    // transposed: [k][row]
    int i0 = blockIdx.y * 64, j0 = blockIdx.x * 64;
    int tid = threadIdx.x;
    for (int l = tid; l < 1024; l += 256) {
        int r = l >> 4, k = l & 15;
        zi[r * 17 + k] = g_z[(size_t)(i0 + r) * 16 + k];
    }
    // zjT: float4 load per thread, scatter 4 rows (conflict-free: lanes span r)
    {
        int r = tid & 63, cq = tid >> 6;     // 256 threads: 64 rows x 4 k-quads
        float4 v = *reinterpret_cast<const float4*>(g_z + (size_t)(j0 + r) * 16 + cq * 4);
        zjT[cq * 4 + 0][r] = v.x;
        zjT[cq * 4 + 1][r] = v.y;
        zjT[cq * 4 + 2][r] = v.z;
        zjT[cq * 4 + 3][r] = v.w;
    }
    __syncthreads();
    int ty = tid >> 4, tx = tid & 15;
    unsigned long long acc2[4][2] = {};      // [i][j2]: packed (col 2*j2, 2*j2+1)
    #pragma unroll
    for (int k = 0; k < 16; ++k) {
        unsigned long long av2[4], bv2[2];
        #pragma unroll
        for (int i = 0; i < 4; ++i) {
            uint32_t ab = __float_as_uint(zi[(ty * 4 + i) * 17 + k]);
            asm("mov.b64 %0, {%1, %1};" : "=l"(av2[i]) : "r"(ab));
        }
        bv2[0] = *reinterpret_cast<const unsigned long long*>(&zjT[k][tx * 4]);
        bv2[1] = *reinterpret_cast<const unsigned long long*>(&zjT[k][tx * 4 + 2]);
        #pragma unroll
        for (int i = 0; i < 4; ++i) {
            asm("fma.rn.f32x2 %0, %1, %2, %0;" : "+l"(acc2[i][0]) : "l"(av2[i]), "l"(bv2[0]));
            asm("fma.rn.f32x2 %0, %1, %2, %0;" : "+l"(acc2[i][1]) : "l"(av2[i]), "l"(bv2[1]));
        }
    }
    #pragma unroll
    for (int i = 0; i < 4; ++i) {
        uint32_t a0, a1, a2, a3;
        asm("mov.b64 {%0, %1}, %2;" : "=r"(a0), "=r"(a1) : "l"(acc2[i][0]));
        asm("mov.b64 {%0, %1}, %2;" : "=r"(a2), "=r"(a3) : "l"(acc2[i][1]));
        float4 v = make_float4(__uint_as_float(a0), __uint_as_float(a1),
                               __uint_as_float(a2), __uint_as_float(a3));
        *reinterpret_cast<float4*>(out + (size_t)(i0 + ty * 4 + i) * NN + j0 + tx * 4) = v;
    }
}

// ---------------- launch ------------------------------------------------
extern "C" void kernel_launch(void* const* d_in, const int* in_sizes, int n_in,
                              void* d_out, int out_size) {
    const float* x       = (const float*)d_in[0];
    const float* adj     = (const float*)d_in[1];
    const float* W_heads = (const float*)d_in[2];
    const float* a_heads = (const float*)d_in[3];
    const float* W_att   = (const float*)d_in[4];
    const float* a_att   = (const float*)d_in[5];
    const float* W1      = (const float*)d_in[6];
    const float* W2      = (const float*)d_in[7];
    const float* W3      = (const float*)d_in[8];
    const float* eps     = (const float*)d_in[9];
    float* out = (float*)d_out;
    (void)in_sizes; (void)n_in; (void)out_size;

    k_build_csr<<<NN / 8, 256>>>(adj);
    k_prep_x<<<(NN * DD / 4) / 256, 256>>>(x);
    k_prep_w<<<(HH * DD * F1V + 256 * F1V) / 256, 256>>>(W_heads, W_att);
    k_gemm_tc<32><<<dim3(NN / 64, 2), 256>>>(a_heads, DD, 0);
    k_gat_aggr<<<(NN * HH) / 8, 256>>>(W1, 0);
    k_gemm_tc<16><<<dim3(NN / 64, 1), 256>>>(a_att, 256, 1);
    k_gat_aggr<<<NN / 8, 256>>>(W1, 1);
    k_nbr_t23<<<NN / 8, 256>>>(W2, W3);
    k_final<<<NN / 8, 256>>>(eps, out);
    k_adjrec<<<dim3(NN / 64, NN / 64), 256>>>(out);
}

// round 13
// speedup vs baseline: 1.1183x; 1.1183x over previous
#include <cuda_runtime.h>
#include <cuda_bf16.h>
#include <cstdint>

#define NN 4096
#define DD 512
#define F1V 64
#define HH 4
#define MAXNBR 128

__device__ __forceinline__ uint32_t smem_u32(const void* p) {
    uint32_t a;
    asm("{ .reg .u64 t; cvta.to.shared.u64 t, %1; cvt.u32.u64 %0, t; }" : "=r"(a) : "l"(p));
    return a;
}
__device__ __forceinline__ void mma_bf16(float* c, const uint32_t* a, const uint32_t* b) {
    asm volatile(
        "mma.sync.aligned.m16n8k16.row.col.f32.bf16.bf16.f32 "
        "{%0,%1,%2,%3}, {%4,%5,%6,%7}, {%8,%9}, {%0,%1,%2,%3};"
        : "+f"(c[0]), "+f"(c[1]), "+f"(c[2]), "+f"(c[3])
        : "r"(a[0]), "r"(a[1]), "r"(a[2]), "r"(a[3]), "r"(b[0]), "r"(b[1]));
}
__device__ __forceinline__ void ldsm4(uint32_t* r, uint32_t addr) {
    asm volatile("ldmatrix.sync.aligned.m8n8.x4.shared.b16 {%0,%1,%2,%3}, [%4];"
        : "=r"(r[0]), "=r"(r[1]), "=r"(r[2]), "=r"(r[3]) : "r"(addr));
}
__device__ __forceinline__ void split_bf(float f, unsigned short& hi, unsigned short& lo) {
    __nv_bfloat16 h = __float2bfloat16(f);
    float r = f - __bfloat162float(h);
    __nv_bfloat16 l = __float2bfloat16(r);
    hi = *reinterpret_cast<unsigned short*>(&h);
    lo = *reinterpret_cast<unsigned short*>(&l);
}
#define CP_ASYNC16(sa, gp) \
    asm volatile("cp.async.cg.shared.global [%0], [%1], 16;" :: "r"(sa), "l"(gp) : "memory")
#define CP_COMMIT() asm volatile("cp.async.commit_group;" ::: "memory")
#define CP_WAIT2()  asm volatile("cp.async.wait_group 2;" ::: "memory")

// ---------------- device scratch (static, no allocation) ----------------
__device__ int      g_cnt[NN];
__device__ int      g_cols[NN * MAXNBR];
__device__ uint16_t g_xhi[NN * DD];
__device__ uint16_t g_xlo[NN * DD];
__device__ uint16_t g_Wthi[HH * F1V * DD];     // [h][n][k] transposed = [256][512]
__device__ uint16_t g_Wtlo[HH * F1V * DD];
__device__ uint16_t g_Wathi[F1V * 256];        // [n][k] = [64][256]
__device__ uint16_t g_Watlo[F1V * 256];
__device__ float    g_Wh[HH * NN * F1V];       // [h][n][64]
__device__ float    g_src[HH * NN];
__device__ float    g_dst[HH * NN];
__device__ uint16_t g_cat_hi[NN * 256];        // [n][h*64+f]
__device__ uint16_t g_cat_lo[NN * 256];
__device__ float    g_Whc[NN * F1V];
__device__ float    g_srcc[NN];
__device__ float    g_dstc[NN];
__device__ float    g_t1[NN * 32];
__device__ float    g_t23[NN * 32];
__device__ float    g_z[NN * 16];

// ---------------- 1: fused CSR build + x split + W split ----------------
// blocks [0,512): csr; [512,2560): prep_x; [2560,3136): prep_w
__global__ void k_prep_all(const float* __restrict__ adj, const float* __restrict__ x,
                           const float* __restrict__ W_heads, const float* __restrict__ W_att) {
    int b = blockIdx.x;
    int tid = threadIdx.x;
    if (b < 512) {
        int wid = tid >> 5, lane = tid & 31;
        int row = b * 8 + wid;
        const float4* arow = reinterpret_cast<const float4*>(adj + (size_t)row * NN);
        int cnt = 0;
        int* cols = g_cols + row * MAXNBR;
        for (int step = 0; step < 32; ++step) {
            float4 v = arow[step * 32 + lane];
            float vals[4] = {v.x, v.y, v.z, v.w};
            #pragma unroll
            for (int e = 0; e < 4; ++e) {
                bool p = vals[e] > 0.0f;
                unsigned m = __ballot_sync(0xffffffffu, p);
                if (p) {
                    int pos = cnt + __popc(m & ((1u << lane) - 1u));
                    if (pos < MAXNBR) cols[pos] = (step * 32 + lane) * 4 + e;
                }
                cnt += __popc(m);
            }
        }
        if (lane == 0) g_cnt[row] = cnt > MAXNBR ? MAXNBR : cnt;
    } else if (b < 2560) {
        int idx = (b - 512) * 256 + tid;
        float4 v = reinterpret_cast<const float4*>(x)[idx];
        unsigned short h0, l0, h1, l1, h2, l2, h3, l3;
        split_bf(v.x, h0, l0); split_bf(v.y, h1, l1);
        split_bf(v.z, h2, l2); split_bf(v.w, h3, l3);
        uint2 hv = make_uint2((uint32_t)h0 | ((uint32_t)h1 << 16),
                              (uint32_t)h2 | ((uint32_t)h3 << 16));
        uint2 lv = make_uint2((uint32_t)l0 | ((uint32_t)l1 << 16),
                              (uint32_t)l2 | ((uint32_t)l3 << 16));
        reinterpret_cast<uint2*>(g_xhi)[idx] = hv;
        reinterpret_cast<uint2*>(g_xlo)[idx] = lv;
    } else {
        int idx = (b - 2560) * 256 + tid;
        if (idx < HH * DD * F1V) {
            int n = idx & 63, k = (idx >> 6) & 511, h = idx >> 15;
            unsigned short hi, lo;
            split_bf(W_heads[idx], hi, lo);
            int o = (h * F1V + n) * DD + k;
            g_Wthi[o] = hi; g_Wtlo[o] = lo;
        } else {
            int i2 = idx - HH * DD * F1V;   // [256][64]
            int n = i2 & 63, k = i2 >> 6;
            unsigned short hi, lo;
            split_bf(W_att[i2], hi, lo);
            int o = n * 256 + k;
            g_Wathi[o] = hi; g_Watlo[o] = lo;
        }
    }
}

// ---------------- 2: cp.async 4-stage distance-3 mma GEMM + src/dst -----
// M=64, N=64 per CTA (blockIdx.y = head). k-chunk 16.
// stage (8192B): Ahi@0, Alo@2048, Bhi@4096, Blo@6144; rows 32B, XOR swizzle.
// Each thread owns 1 A unit + 1 B unit (16B), pointers precomputed.
__global__ void __launch_bounds__(256)
k_gemm_tc(const float* __restrict__ avec, int K, int sel) {
    __shared__ __align__(16) unsigned char sm[4 * 8192];
    __shared__ float s_av[128];
    __shared__ float s_sp[4][64];
    __shared__ float s_dp[4][64];

    int tid = threadIdx.x;
    int w = tid >> 5, lane = tid & 31;
    int MW = (w & 1) * 32;
    int nw = w >> 1;
    int NW = nw * 16;
    int g = lane >> 2, t = lane & 3;
    int head = blockIdx.y;
    int m0 = blockIdx.x * 64;

    const uint16_t *Ahi, *Alo, *Bhi, *Blo;
    float *oWh, *oSrc, *oDst;
    if (sel == 0) {
        Ahi = g_xhi; Alo = g_xlo;
        Bhi = g_Wthi + (size_t)head * F1V * DD;
        Blo = g_Wtlo + (size_t)head * F1V * DD;
        oWh = g_Wh + (size_t)head * NN * F1V;
        oSrc = g_src + head * NN; oDst = g_dst + head * NN;
    } else {
        Ahi = g_cat_hi; Alo = g_cat_lo; Bhi = g_Wathi; Blo = g_Watlo;
        oWh = g_Whc; oSrc = g_srcc; oDst = g_dstc;
    }
    if (tid < 128) s_av[tid] = avec[head * 128 + tid];

    uint32_t smb = smem_u32(sm);
    int nch = K >> 4;

    // per-thread load slots: side = tid>>7, r = (tid&127)>>1, u = tid&1
    int side = tid >> 7, rT = (tid & 127) >> 1, uT = tid & 1;
    int swz = ((uT ^ ((rT >> 2) & 1))) << 4;
    const uint16_t* gpA = (side ? Alo : Ahi) + (size_t)(m0 + rT) * K + uT * 8;
    const uint16_t* gpB = (side ? Blo : Bhi) + (size_t)rT * K + uT * 8;
    uint32_t saA = smb + side * 2048 + rT * 32 + swz;
    uint32_t saB = smb + 4096 + side * 2048 + rT * 32 + swz;

    // LDSM offsets (stage-relative)
    int rA = MW + (lane & 15), uA = lane >> 4;
    int offA = rA * 32 + (((uA ^ ((rA >> 2) & 1))) << 4);
    int rB = NW + ((lane >> 4) << 3) + (lane & 7), uB = (lane >> 3) & 1;
    int offB = 4096 + rB * 32 + (((uB ^ ((rB >> 2) & 1))) << 4);

    float acc[2][2][4] = {};

    // prologue: chunks 0,1,2 -> stages 0,1,2
    #pragma unroll
    for (int c = 0; c < 3; ++c) {
        CP_ASYNC16(saA + c * 8192, gpA + c * 16);
        CP_ASYNC16(saB + c * 8192, gpB + c * 16);
        CP_COMMIT();
    }

    for (int c = 0; c < nch; ++c) {
        CP_WAIT2();
        __syncthreads();
        if (c + 3 < nch) {
            int s3 = ((c + 3) & 3) * 8192;
            CP_ASYNC16(saA + s3, gpA + (c + 3) * 16);
            CP_ASYNC16(saB + s3, gpB + (c + 3) * 16);
        }
        CP_COMMIT();

        uint32_t st = smb + (c & 3) * 8192;
        uint32_t ah[2][4], al[2][4], bh[4], bl[4];
        ldsm4(ah[0], st + offA);
        ldsm4(ah[1], st + offA + 512);
        ldsm4(al[0], st + 2048 + offA);
        ldsm4(al[1], st + 2048 + offA + 512);
        ldsm4(bh, st + offB);
        ldsm4(bl, st + 2048 + offB);
        #pragma unroll
        for (int i = 0; i < 2; ++i)
            #pragma unroll
            for (int q = 0; q < 2; ++q) {
                float* cc = acc[i][q];
                mma_bf16(cc, ah[i], &bh[q * 2]);
                mma_bf16(cc, al[i], &bh[q * 2]);
                mma_bf16(cc, ah[i], &bl[q * 2]);
            }
    }

    // epilogue: write Wh + fused src/dst partials
    #pragma unroll
    for (int i = 0; i < 2; ++i) {
        int r0 = MW + i * 16 + g;
        float sp0 = 0, sp1 = 0, dp0 = 0, dp1 = 0;
        #pragma unroll
        for (int q = 0; q < 2; ++q) {
            int cb = NW + q * 8 + 2 * t;
            *reinterpret_cast<float2*>(oWh + (size_t)(m0 + r0) * 64 + cb) =
                make_float2(acc[i][q][0], acc[i][q][1]);
            *reinterpret_cast<float2*>(oWh + (size_t)(m0 + r0 + 8) * 64 + cb) =
                make_float2(acc[i][q][2], acc[i][q][3]);
            float a0s = s_av[cb], a1s = s_av[cb + 1];
            float a0d = s_av[64 + cb], a1d = s_av[64 + cb + 1];
            sp0 += acc[i][q][0] * a0s + acc[i][q][1] * a1s;
            sp1 += acc[i][q][2] * a0s + acc[i][q][3] * a1s;
            dp0 += acc[i][q][0] * a0d + acc[i][q][1] * a1d;
            dp1 += acc[i][q][2] * a0d + acc[i][q][3] * a1d;
        }
        #pragma unroll
        for (int off = 1; off < 4; off <<= 1) {
            sp0 += __shfl_xor_sync(0xffffffffu, sp0, off);
            sp1 += __shfl_xor_sync(0xffffffffu, sp1, off);
            dp0 += __shfl_xor_sync(0xffffffffu, dp0, off);
            dp1 += __shfl_xor_sync(0xffffffffu, dp1, off);
        }
        if (t == 0) {
            s_sp[nw][r0] = sp0; s_sp[nw][r0 + 8] = sp1;
            s_dp[nw][r0] = dp0; s_dp[nw][r0 + 8] = dp1;
        }
    }
    __syncthreads();
    if (tid < 64) {
        oSrc[m0 + tid] = s_sp[0][tid] + s_sp[1][tid] + s_sp[2][tid] + s_sp[3][tid];
        oDst[m0 + tid] = s_dp[0][tid] + s_dp[1][tid] + s_dp[2][tid] + s_dp[3][tid];
    }
}

// ---------------- 3: sparse GAT softmax + aggregate + ELU ---------------
__global__ void k_gat_aggr(const float* __restrict__ W1, int sel) {
    __shared__ float s_w[8][MAXNBR];
    __shared__ int   s_c[8][MAXNBR];
    int wid = threadIdx.x >> 5, lane = threadIdx.x & 31;
    int wg = blockIdx.x * 8 + wid;
    int h, row;
    if (sel) { h = 0; row = wg; } else { h = wg & 3; row = wg >> 2; }
    const float* Wh  = sel ? g_Whc  : g_Wh;
    const float* src = sel ? g_srcc : g_src;
    const float* dst = sel ? g_dstc : g_dst;

    int cnt = g_cnt[row];
    const int* cols = g_cols + row * MAXNBR;
    float si = src[h * NN + row];
    const float* dsth = dst + (size_t)h * NN;

    float sum = 0.0f;
    #pragma unroll
    for (int tt = 0; tt < 4; ++tt) {
        int idx = tt * 32 + lane;
        float e = 0.0f; int c = 0;
        if (idx < cnt) {
            c = cols[idx];
            float v = si + __ldg(dsth + c);
            v = v > 0.0f ? v : 0.2f * v;           // LeakyReLU (logits bounded -> no max)
            e = __expf(v);
        }
        s_w[wid][idx] = e;
        s_c[wid][idx] = c;
        sum += e;
    }
    #pragma unroll
    for (int o = 16; o; o >>= 1) sum += __shfl_xor_sync(0xffffffffu, sum, o);
    float inv = 1.0f / sum;
    __syncwarp();

    int half = lane >> 4, li = lane & 15;
    const float* WhhB = Wh + (size_t)h * NN * 64;
    float4 A0 = {0, 0, 0, 0}, A1 = {0, 0, 0, 0};
    int cntR = (cnt + 3) & ~3;
    for (int j = 0; j < cntR; j += 4) {
        int   c0 = s_c[wid][j + half],     c1 = s_c[wid][j + 2 + half];
        float w0 = s_w[wid][j + half],     w1 = s_w[wid][j + 2 + half];
        float4 v0 = __ldg(reinterpret_cast<const float4*>(WhhB + (size_t)c0 * 64) + li);
        float4 v1 = __ldg(reinterpret_cast<const float4*>(WhhB + (size_t)c1 * 64) + li);
        A0.x += w0 * v0.x; A0.y += w0 * v0.y; A0.z += w0 * v0.z; A0.w += w0 * v0.w;
        A1.x += w1 * v1.x; A1.y += w1 * v1.y; A1.z += w1 * v1.z; A1.w += w1 * v1.w;
    }
    float4 A;
    A.x = A0.x + A1.x; A.y = A0.y + A1.y; A.z = A0.z + A1.z; A.w = A0.w + A1.w;
    A.x += __shfl_xor_sync(0xffffffffu, A.x, 16);
    A.y += __shfl_xor_sync(0xffffffffu, A.y, 16);
    A.z += __shfl_xor_sync(0xffffffffu, A.z, 16);
    A.w += __shfl_xor_sync(0xffffffffu, A.w, 16);
    A.x *= inv; A.y *= inv; A.z *= inv; A.w *= inv;
    A.x = A.x > 0.0f ? A.x : __expf(A.x) - 1.0f;   // ELU
    A.y = A.y > 0.0f ? A.y : __expf(A.y) - 1.0f;
    A.z = A.z > 0.0f ? A.z : __expf(A.z) - 1.0f;
    A.w = A.w > 0.0f ? A.w : __expf(A.w) - 1.0f;

    if (sel == 0) {
        if (half == 0) {
            unsigned short h0, l0, h1, l1, h2, l2, h3, l3;
            split_bf(A.x, h0, l0); split_bf(A.y, h1, l1);
            split_bf(A.z, h2, l2); split_bf(A.w, h3, l3);
            int o2 = row * 64 + h * 16 + li;
            reinterpret_cast<uint2*>(g_cat_hi)[o2] =
                make_uint2((uint32_t)h0 | ((uint32_t)h1 << 16),
                           (uint32_t)h2 | ((uint32_t)h3 << 16));
            reinterpret_cast<uint2*>(g_cat_lo)[o2] =
                make_uint2((uint32_t)l0 | ((uint32_t)l1 << 16),
                           (uint32_t)l2 | ((uint32_t)l3 << 16));
        }
    } else {
        float acc = 0.0f;
        #pragma unroll
        for (int li2 = 0; li2 < 16; ++li2) {
            float w0 = __shfl_sync(0xffffffffu, A.x, li2);
            float w1 = __shfl_sync(0xffffffffu, A.y, li2);
            float w2 = __shfl_sync(0xffffffffu, A.z, li2);
            float w3 = __shfl_sync(0xffffffffu, A.w, li2);
            int kb = li2 * 4;
            acc += w0 * W1[kb * 32 + lane] + w1 * W1[(kb + 1) * 32 + lane]
                 + w2 * W1[(kb + 2) * 32 + lane] + w3 * W1[(kb + 3) * 32 + lane];
        }
        g_t1[(size_t)row * 32 + lane] = acc;
    }
}

// ---------------- 4: h1 = relu(nbrsum(t1)); t23 = h1@[W2|W3] ------------
__global__ void k_nbr_t23(const float* __restrict__ W2, const float* __restrict__ W3) {
    int wid = threadIdx.x >> 5, lane = threadIdx.x & 31;
    int row = blockIdx.x * 8 + wid;
    int cnt = g_cnt[row];
    const int* cols = g_cols + row * MAXNBR;
    float acc = 0.0f;
    for (int jj = 0; jj < cnt; ++jj) {
        int c = cols[jj];
        acc += g_t1[(size_t)c * 32 + lane];
    }
    float hv = fmaxf(acc, 0.0f);
    const float* W = (lane < 16) ? W2 : W3;
    int f = lane & 15;
    float acc2 = 0.0f;
    #pragma unroll
    for (int k = 0; k < 32; ++k) {
        float h = __shfl_sync(0xffffffffu, hv, k);
        acc2 += h * W[k * 16 + f];
    }
    g_t23[(size_t)row * 32 + lane] = acc2;
}

// ---------------- 5: mu/logvar = nbrsum, z = eps*exp(lv)+mu -------------
__global__ void k_final(const float* __restrict__ eps, float* __restrict__ out) {
    int wid = threadIdx.x >> 5, lane = threadIdx.x & 31;
    int row = blockIdx.x * 8 + wid;
    int cnt = g_cnt[row];
    const int* cols = g_cols + row * MAXNBR;
    float acc = 0.0f;
    for (int j = 0; j < cnt; ++j) {
        int c = cols[j];
        acc += g_t23[(size_t)c * 32 + lane];
    }
    float other = __shfl_xor_sync(0xffffffffu, acc, 16);
    size_t NNq = (size_t)NN * NN;
    if (lane < 16) {
        out[NNq + (size_t)row * 16 + lane] = acc;                          // mu
        float zz = eps[(size_t)row * 16 + lane] * __expf(other) + acc;
        g_z[(size_t)row * 16 + lane] = zz;
    } else {
        out[NNq + (size_t)NN * 16 + (size_t)row * 16 + (lane - 16)] = acc; // logvar
    }
}

// ---------------- 6: adj_rec = z @ z^T (packed f32x2 FMA) ---------------
__global__ void k_adjrec(float* __restrict__ out) {
    __shared__ float zi[64 * 17];
    __shared__ float zjT[16][64];    // transposed: [k][row]
    int i0 = blockIdx.y * 64, j0 = blockIdx.x * 64;
    int tid = threadIdx.x;
    for (int l = tid; l < 1024; l += 256) {
        int r = l >> 4, k = l & 15;
        zi[r * 17 + k] = g_z[(size_t)(i0 + r) * 16 + k];
    }
    {
        int r = tid & 63, cq = tid >> 6;
        float4 v = *reinterpret_cast<const float4*>(g_z + (size_t)(j0 + r) * 16 + cq * 4);
        zjT[cq * 4 + 0][r] = v.x;
        zjT[cq * 4 + 1][r] = v.y;
        zjT[cq * 4 + 2][r] = v.z;
        zjT[cq * 4 + 3][r] = v.w;
    }
    __syncthreads();
    int ty = tid >> 4, tx = tid & 15;
    unsigned long long acc2[4][2] = {};
    #pragma unroll
    for (int k = 0; k < 16; ++k) {
        unsigned long long av2[4], bv2[2];
        #pragma unroll
        for (int i = 0; i < 4; ++i) {
            uint32_t ab = __float_as_uint(zi[(ty * 4 + i) * 17 + k]);
            asm("mov.b64 %0, {%1, %1};" : "=l"(av2[i]) : "r"(ab));
        }
        bv2[0] = *reinterpret_cast<const unsigned long long*>(&zjT[k][tx * 4]);
        bv2[1] = *reinterpret_cast<const unsigned long long*>(&zjT[k][tx * 4 + 2]);
        #pragma unroll
        for (int i = 0; i < 4; ++i) {
            asm("fma.rn.f32x2 %0, %1, %2, %0;" : "+l"(acc2[i][0]) : "l"(av2[i]), "l"(bv2[0]));
            asm("fma.rn.f32x2 %0, %1, %2, %0;" : "+l"(acc2[i][1]) : "l"(av2[i]), "l"(bv2[1]));
        }
    }
    #pragma unroll
    for (int i = 0; i < 4; ++i) {
        uint32_t a0, a1, a2, a3;
        asm("mov.b64 {%0, %1}, %2;" : "=r"(a0), "=r"(a1) : "l"(acc2[i][0]));
        asm("mov.b64 {%0, %1}, %2;" : "=r"(a2), "=r"(a3) : "l"(acc2[i][1]));
        float4 v = make_float4(__uint_as_float(a0), __uint_as_float(a1),
                               __uint_as_float(a2), __uint_as_float(a3));
        *reinterpret_cast<float4*>(out + (size_t)(i0 + ty * 4 + i) * NN + j0 + tx * 4) = v;
    }
}

// ---------------- launch ------------------------------------------------
extern "C" void kernel_launch(void* const* d_in, const int* in_sizes, int n_in,
                              void* d_out, int out_size) {
    const float* x       = (const float*)d_in[0];
    const float* adj     = (const float*)d_in[1];
    const float* W_heads = (const float*)d_in[2];
    const float* a_heads = (const float*)d_in[3];
    const float* W_att   = (const float*)d_in[4];
    const float* a_att   = (const float*)d_in[5];
    const float* W1      = (const float*)d_in[6];
    const float* W2      = (const float*)d_in[7];
    const float* W3      = (const float*)d_in[8];
    const float* eps     = (const float*)d_in[9];
    float* out = (float*)d_out;
    (void)in_sizes; (void)n_in; (void)out_size;

    k_prep_all<<<3136, 256>>>(adj, x, W_heads, W_att);
    k_gemm_tc<<<dim3(NN / 64, HH), 256>>>(a_heads, DD, 0);
    k_gat_aggr<<<(NN * HH) / 8, 256>>>(W1, 0);
    k_gemm_tc<<<dim3(NN / 64, 1), 256>>>(a_att, 256, 1);
    k_gat_aggr<<<NN / 8, 256>>>(W1, 1);
    k_nbr_t23<<<NN / 8, 256>>>(W2, W3);
    k_final<<<NN / 8, 256>>>(eps, out);
    k_adjrec<<<dim3(NN / 64, NN / 64), 256>>>(out);
}